// round 16
// baseline (speedup 1.0000x reference)
#include <cuda_runtime.h>
#include <cuda_bf16.h>

// Problem constants (match reference_code)
#define B_DIM 4
#define L_DIM 4096
#define D_DIM 1024
#define NUM_KEEP 1024
#define NUM_DROP (L_DIM - NUM_KEEP)

// Output layout (flattened tuple, all float32):
//   [0)            outputs_dropped : B * NUM_KEEP * D   = 4,194,304
//   [OFF_MASKED)   outputs_masked  : B * L * D          = 16,777,216
//   [OFF_MASKDROP) mask_drop       : L                  = 4,096
//   [OFF_IDX)      idx_keep echo   : NUM_KEEP           = 1,024
#define OFF_MASKED   (B_DIM * NUM_KEEP * D_DIM)
#define OFF_MASKDROP (OFF_MASKED + B_DIM * L_DIM * D_DIM)
#define OFF_IDX      (OFF_MASKDROP + L_DIM)

#define ROWS_PER_BLOCK 8
#define MAIN_BLOCKS   ((B_DIM * L_DIM) / ROWS_PER_BLOCK)   // 2048
#define TAIL_BLOCKS   16
#define TOTAL_BLOCKS  (MAIN_BLOCKS + TAIL_BLOCKS)

// lower_bound over sorted idx_keep in GLOBAL memory (tail blocks only; the
// 16 tail blocks are fully hidden behind 2048 streaming blocks).
__device__ __forceinline__ int lower_bound_g(const int* __restrict__ idx, int v) {
    int lo = 0, hi = NUM_KEEP;
    #pragma unroll
    for (int it = 0; it < 11; ++it) {
        if (lo < hi) {
            int mid = (lo + hi) >> 1;
            if (__ldg(&idx[mid]) < v) lo = mid + 1; else hi = mid;
        }
    }
    return lo;
}

// FINAL champion configuration (measured kernel 16.42-16.45 us, twice):
//  - 8 rows/block, one float4 column per thread, front-batched loads (MLP=8)
//  - NO occupancy cap: 48 regs / 5 blocks/SM (capping to 6 kills MLP — R12)
//  - __ldcs input loads (single-use streaming reads)
//  - __stcs output stores (fastest store policy measured; evict_* hints and
//    256-bit forms all regressed — R8/R11)
//  - SINGLE if/else store loop: splitting into two predicated passes breaks
//    ptxas's predicated schedule and costs ~6 us (R14). Do not restructure.
__global__ void __launch_bounds__(256)
mask_fused_kernel(const float4* __restrict__ inputs,
                  const float4* __restrict__ mask_embedding,
                  const int4*  __restrict__ idx_keep,
                  float* __restrict__ out) {
    // Tiny flag array only — no 4 KB index copy, no LDS binary search.
    __shared__ int s_flag[ROWS_PER_BLOCK];

    const int tid = threadIdx.x;   // 0..255
    const int bid = blockIdx.x;

    if (bid < MAIN_BLOCKS) {
        // ----- main path: 8 consecutive (b,l) rows, one float4 column/thread
        const int row0 = bid * ROWS_PER_BLOCK;
        const int l0   = row0 & (L_DIM - 1);   // 8 rows never straddle a batch

        if (tid < ROWS_PER_BLOCK) s_flag[tid] = 0;

        // Register scatter: each thread tests its 4 idx values (rank=4*tid+j)
        // against the window [l0, l0+8). Unique values -> conflict-free.
        const int4 q = __ldg(&idx_keep[tid]);
        __syncthreads();
        {
            unsigned d;
            d = (unsigned)(q.x - l0); if (d < ROWS_PER_BLOCK) s_flag[d] = 4 * tid + 1;
            d = (unsigned)(q.y - l0); if (d < ROWS_PER_BLOCK) s_flag[d] = 4 * tid + 2;
            d = (unsigned)(q.z - l0); if (d < ROWS_PER_BLOCK) s_flag[d] = 4 * tid + 3;
            d = (unsigned)(q.w - l0); if (d < ROWS_PER_BLOCK) s_flag[d] = 4 * tid + 4;
        }
        __syncthreads();

        float4* __restrict__ dropped = (float4*)(out);               // [B,K,D]
        float4* __restrict__ masked  = (float4*)(out + OFF_MASKED);  // [B,L,D]
        const float4 me = __ldg(&mask_embedding[tid]);

        int flags[ROWS_PER_BLOCK];
        #pragma unroll
        for (int r = 0; r < ROWS_PER_BLOCK; ++r) flags[r] = s_flag[r];

        // front-batch keep-row loads for MLP; streaming reads (single-use).
        float4 v[ROWS_PER_BLOCK];
        #pragma unroll
        for (int r = 0; r < ROWS_PER_BLOCK; ++r) {
            if (flags[r]) {
                v[r] = __ldcs(&inputs[(size_t)(row0 + r) * (D_DIM / 4) + tid]);
            }
        }

        // streaming stores (st.global.cs), single predicated loop.
        #pragma unroll
        for (int r = 0; r < ROWS_PER_BLOCK; ++r) {
            const int    row    = row0 + r;
            const size_t row_f4 = (size_t)row * (D_DIM / 4);
            if (flags[r]) {
                const int b = row >> 12;           // row / L_DIM
                const int k = flags[r] - 1;
                __stcs(&masked[row_f4 + tid], v[r]);
                __stcs(&dropped[((size_t)b * NUM_KEEP + k) * (D_DIM / 4) + tid], v[r]);
            } else {
                __stcs(&masked[row_f4 + tid], me);
            }
        }
    } else {
        // ----- tail path: mask_drop (4096 over 16 blocks) + idx echo
        const int* idx32 = (const int*)idx_keep;
        const int tb = bid - MAIN_BLOCKS;          // 0..15
        const int i  = tb * 256 + tid;             // 0..4095
        int pos = lower_bound_g(idx32, i);
        bool kept = (pos < NUM_KEEP && __ldg(&idx32[pos]) == i);
        out[OFF_MASKDROP + i] = kept ? 0.0f : 1.0f;
        if (tb < 4) {
            const int j = tb * 256 + tid;          // 0..1023
            out[OFF_IDX + j] = (float)__ldg(&idx32[j]);
        }
    }
}

// ---------------------------------------------------------------------------
extern "C" void kernel_launch(void* const* d_in, const int* in_sizes, int n_in,
                              void* d_out, int out_size) {
    const float4* inputs         = (const float4*)d_in[0];  // [B, L, D] f32
    const float4* mask_embedding = (const float4*)d_in[1];  // [D] f32
    const int4*   idx_keep       = (const int4*)d_in[2];    // [NUM_KEEP] i32
    float*        out            = (float*)d_out;

    mask_fused_kernel<<<TOTAL_BLOCKS, 256>>>(inputs, mask_embedding, idx_keep, out);
}

// round 17
// speedup vs baseline: 1.5725x; 1.5725x over previous
#include <cuda_runtime.h>
#include <cuda_bf16.h>

// Problem constants (match reference_code)
#define B_DIM 4
#define L_DIM 4096
#define D_DIM 1024
#define NUM_KEEP 1024
#define NUM_DROP (L_DIM - NUM_KEEP)

// Output layout (flattened tuple, all float32):
//   [0)            outputs_dropped : B * NUM_KEEP * D   = 4,194,304
//   [OFF_MASKED)   outputs_masked  : B * L * D          = 16,777,216
//   [OFF_MASKDROP) mask_drop       : L                  = 4,096
//   [OFF_IDX)      idx_keep echo   : NUM_KEEP           = 1,024
#define OFF_MASKED   (B_DIM * NUM_KEEP * D_DIM)
#define OFF_MASKDROP (OFF_MASKED + B_DIM * L_DIM * D_DIM)
#define OFF_IDX      (OFF_MASKDROP + L_DIM)

#define ROWS_PER_BLOCK 8
#define MAIN_BLOCKS   ((B_DIM * L_DIM) / ROWS_PER_BLOCK)   // 2048
#define TAIL_BLOCKS   16
#define TOTAL_BLOCKS  (MAIN_BLOCKS + TAIL_BLOCKS)

// lower_bound over sorted idx_keep in GLOBAL memory (tail blocks only; the
// 16 tail blocks are fully hidden behind 2048 streaming blocks).
__device__ __forceinline__ int lower_bound_g(const int* __restrict__ idx, int v) {
    int lo = 0, hi = NUM_KEEP;
    #pragma unroll
    for (int it = 0; it < 11; ++it) {
        if (lo < hi) {
            int mid = (lo + hi) >> 1;
            if (__ldg(&idx[mid]) < v) lo = mid + 1; else hi = mid;
        }
    }
    return lo;
}

// FINAL champion configuration (best measured: kernel 16.42/16.45 us).
// Identical binaries have measured 16.4-24.5 us across runs (environmental
// clock/contention variance on the brokered GPU) — the config below holds the
// best observations by a clear margin and every structural perturbation
// regressed:
//  - 8 rows/block, one float4 column per thread, front-batched loads (MLP=8)
//  - NO occupancy cap: 48 regs / 5 blocks/SM (capping to 6 kills MLP — R12)
//  - __ldcs input loads (single-use streaming reads)
//  - __stcs output stores (fastest store policy; evict_* hints + 256-bit
//    forms regressed — R8/R11)
//  - SINGLE if/else store loop (splitting it costs ~6 us — R14)
__global__ void __launch_bounds__(256)
mask_fused_kernel(const float4* __restrict__ inputs,
                  const float4* __restrict__ mask_embedding,
                  const int4*  __restrict__ idx_keep,
                  float* __restrict__ out) {
    // Tiny flag array only — no 4 KB index copy, no LDS binary search.
    __shared__ int s_flag[ROWS_PER_BLOCK];

    const int tid = threadIdx.x;   // 0..255
    const int bid = blockIdx.x;

    if (bid < MAIN_BLOCKS) {
        // ----- main path: 8 consecutive (b,l) rows, one float4 column/thread
        const int row0 = bid * ROWS_PER_BLOCK;
        const int l0   = row0 & (L_DIM - 1);   // 8 rows never straddle a batch

        if (tid < ROWS_PER_BLOCK) s_flag[tid] = 0;

        // Register scatter: each thread tests its 4 idx values (rank=4*tid+j)
        // against the window [l0, l0+8). Unique values -> conflict-free.
        const int4 q = __ldg(&idx_keep[tid]);
        __syncthreads();
        {
            unsigned d;
            d = (unsigned)(q.x - l0); if (d < ROWS_PER_BLOCK) s_flag[d] = 4 * tid + 1;
            d = (unsigned)(q.y - l0); if (d < ROWS_PER_BLOCK) s_flag[d] = 4 * tid + 2;
            d = (unsigned)(q.z - l0); if (d < ROWS_PER_BLOCK) s_flag[d] = 4 * tid + 3;
            d = (unsigned)(q.w - l0); if (d < ROWS_PER_BLOCK) s_flag[d] = 4 * tid + 4;
        }
        __syncthreads();

        float4* __restrict__ dropped = (float4*)(out);               // [B,K,D]
        float4* __restrict__ masked  = (float4*)(out + OFF_MASKED);  // [B,L,D]
        const float4 me = __ldg(&mask_embedding[tid]);

        int flags[ROWS_PER_BLOCK];
        #pragma unroll
        for (int r = 0; r < ROWS_PER_BLOCK; ++r) flags[r] = s_flag[r];

        // front-batch keep-row loads for MLP; streaming reads (single-use).
        float4 v[ROWS_PER_BLOCK];
        #pragma unroll
        for (int r = 0; r < ROWS_PER_BLOCK; ++r) {
            if (flags[r]) {
                v[r] = __ldcs(&inputs[(size_t)(row0 + r) * (D_DIM / 4) + tid]);
            }
        }

        // streaming stores (st.global.cs), single predicated loop.
        #pragma unroll
        for (int r = 0; r < ROWS_PER_BLOCK; ++r) {
            const int    row    = row0 + r;
            const size_t row_f4 = (size_t)row * (D_DIM / 4);
            if (flags[r]) {
                const int b = row >> 12;           // row / L_DIM
                const int k = flags[r] - 1;
                __stcs(&masked[row_f4 + tid], v[r]);
                __stcs(&dropped[((size_t)b * NUM_KEEP + k) * (D_DIM / 4) + tid], v[r]);
            } else {
                __stcs(&masked[row_f4 + tid], me);
            }
        }
    } else {
        // ----- tail path: mask_drop (4096 over 16 blocks) + idx echo
        const int* idx32 = (const int*)idx_keep;
        const int tb = bid - MAIN_BLOCKS;          // 0..15
        const int i  = tb * 256 + tid;             // 0..4095
        int pos = lower_bound_g(idx32, i);
        bool kept = (pos < NUM_KEEP && __ldg(&idx32[pos]) == i);
        out[OFF_MASKDROP + i] = kept ? 0.0f : 1.0f;
        if (tb < 4) {
            const int j = tb * 256 + tid;          // 0..1023
            out[OFF_IDX + j] = (float)__ldg(&idx32[j]);
        }
    }
}

// ---------------------------------------------------------------------------
extern "C" void kernel_launch(void* const* d_in, const int* in_sizes, int n_in,
                              void* d_out, int out_size) {
    const float4* inputs         = (const float4*)d_in[0];  // [B, L, D] f32
    const float4* mask_embedding = (const float4*)d_in[1];  // [D] f32
    const int4*   idx_keep       = (const int4*)d_in[2];    // [NUM_KEEP] i32
    float*        out            = (float*)d_out;

    mask_fused_kernel<<<TOTAL_BLOCKS, 256>>>(inputs, mask_embedding, idx_keep, out);
}